// round 2
// baseline (speedup 1.0000x reference)
#include <cuda_runtime.h>
#include <cstdint>

#define EKV 30016
__device__ float d_E[EKV];   // E[v] = embedding[v] . context_weight

static __device__ __forceinline__ float wsum(float v) {
#pragma unroll
    for (int o = 16; o; o >>= 1) v += __shfl_xor_sync(0xffffffffu, v, o);
    return v;
}
static __device__ __forceinline__ float wmax(float v) {
#pragma unroll
    for (int o = 16; o; o >>= 1) v = fmaxf(v, __shfl_xor_sync(0xffffffffu, v, o));
    return v;
}

// Pre-kernel: E[v] = embedding[v] . cw   (one warp per vocab row)
__global__ void ek_kernel(const float* __restrict__ emb,
                          const float* __restrict__ cw, int V) {
    int w = (blockIdx.x * blockDim.x + threadIdx.x) >> 5;
    int lane = threadIdx.x & 31;
    if (w >= V || w >= EKV) return;
    float4 e = reinterpret_cast<const float4*>(emb)[w * 32 + lane];
    float4 c = reinterpret_cast<const float4*>(cw)[lane];
    float s = wsum(e.x * c.x + e.y * c.y + e.z * c.z + e.w * c.w);
    if (lane == 0) d_E[w] = s;
}

// Main kernel: one warp per tree, lane owns 4 embedding dims (float4).
// Scalar recursion uses only E-gathers; each embedding row read exactly once.
__global__ __launch_bounds__(256) void tree_kernel(
    const int* __restrict__ tokens, const int* __restrict__ masks,
    const float* __restrict__ emb, float* __restrict__ out, int N, int V) {
    const int lane = threadIdx.x & 31;
    const int n = blockIdx.x * (blockDim.x >> 5) + (threadIdx.x >> 5);
    if (n >= N) return;
    const int vmax = min(V, EKV) - 1;
    const int* tk = tokens + n * 320;
    const int* mk = masks + n * 320;

    // ---------- leaf level d = 7 ----------
    int t0 = tk[7 * 40 + lane];
    bool m0 = mk[7 * 40 + lane] != 0;
    bool v0 = m0 && (t0 >= 0);
    t0 = min(max(t0, 0), vmax);
    int t1 = 0; bool m1 = false, v1 = false;
    if (lane < 8) {
        t1 = tk[7 * 40 + 32 + lane];
        m1 = mk[7 * 40 + 32 + lane] != 0;
        v1 = m1 && (t1 >= 0);
        t1 = min(max(t1, 0), vmax);
    }
    int prev_cnt = __popc(__ballot_sync(0xffffffffu, m0)) +
                   __popc(__ballot_sync(0xffffffffu, (lane < 8) && m1));

    float c0 = v0 ? 1.f : 0.f;
    float c1 = v1 ? 1.f : 0.f;

    float4 acc = make_float4(0.f, 0.f, 0.f, 0.f);
#pragma unroll
    for (int s = 0; s < 40; ++s) {
        float cs = __shfl_sync(0xffffffffu, (s < 32) ? c0 : c1, s & 31);
        int   ts = __shfl_sync(0xffffffffu, (s < 32) ? t0 : t1, s & 31);
        float4 r = reinterpret_cast<const float4*>(emb)[ts * 32 + lane];
        acc.x = fmaf(cs, r.x, acc.x);
        acc.y = fmaf(cs, r.y, acc.y);
        acc.z = fmaf(cs, r.z, acc.z);
        acc.w = fmaf(cs, r.w, acc.w);
    }
    // p = pooled . cw = sum over valid slots of E[token]
    float e0 = d_E[t0];
    float e1 = (lane < 8) ? d_E[t1] : 0.f;
    float p = wsum((v0 ? e0 : 0.f) + (v1 ? e1 : 0.f));

    // ---------- levels d = 6 .. 0 ----------
#pragma unroll 1
    for (int d = 6; d >= 0; --d) {
        t0 = tk[d * 40 + lane];
        m0 = mk[d * 40 + lane] != 0;
        v0 = m0 && (t0 >= 0);
        t0 = min(max(t0, 0), vmax);
        t1 = 0; m1 = false; v1 = false;
        if (lane < 8) {
            t1 = tk[d * 40 + 32 + lane];
            m1 = mk[d * 40 + 32 + lane] != 0;
            v1 = m1 && (t1 >= 0);
            t1 = min(max(t1, 0), vmax);
        }
        int cur_cnt = __popc(__ballot_sync(0xffffffffu, m0)) +
                      __popc(__ballot_sync(0xffffffffu, (lane < 8) && m1));
        int nc = max(prev_cnt, 1);   // child count = masks of level d+1
        prev_cnt = cur_cnt;

        e0 = d_E[t0];
        e1 = (lane < 8) ? d_E[t1] : 0.f;
        float g0 = 1.f / (1.f + __expf(-e0));
        float g1 = 1.f / (1.f + __expf(-e1));
        float cc0 = (v0 && (lane < nc)) ? g0 : 0.f;          // gate * child
        float cc1 = (v1 && (32 + lane < nc)) ? g1 : 0.f;
        float h0 = e0 + cc0 * p;                             // attn logit
        float h1 = e1 + cc1 * p;
        float l0 = v0 ? h0 : -1e38f;
        float l1 = v1 ? h1 : -1e38f;
        float mx = wmax(fmaxf(l0, l1));
        float x0 = v0 ? __expf(h0 - mx) : 0.f;
        float x1 = v1 ? __expf(h1 - mx) : 0.f;
        float Z = wsum(x0 + x1);
        float inv = 1.f / Z;
        float a0 = x0 * inv, a1 = x1 * inv;                  // softmax weights
        float A  = wsum(a0 * cc0 + a1 * cc1);                // Σ a_s cc_s
        float pn = wsum(a0 * h0 + a1 * h1);                  // new pooled . cw

        float4 nacc;
        nacc.x = A * acc.x; nacc.y = A * acc.y;
        nacc.z = A * acc.z; nacc.w = A * acc.w;
#pragma unroll
        for (int s = 0; s < 40; ++s) {
            float cs = __shfl_sync(0xffffffffu, (s < 32) ? a0 : a1, s & 31);
            int   ts = __shfl_sync(0xffffffffu, (s < 32) ? t0 : t1, s & 31);
            float4 r = reinterpret_cast<const float4*>(emb)[ts * 32 + lane];
            nacc.x = fmaf(cs, r.x, nacc.x);
            nacc.y = fmaf(cs, r.y, nacc.y);
            nacc.z = fmaf(cs, r.z, nacc.z);
            nacc.w = fmaf(cs, r.w, nacc.w);
        }
        acc = nacc;
        p = pn;
    }

    reinterpret_cast<float4*>(out)[n * 32 + lane] = acc;
}

extern "C" void kernel_launch(void* const* d_in, const int* in_sizes, int n_in,
                              void* d_out, int out_size) {
    const int*   tokens = (const int*)d_in[0];
    const int*   masks  = (const int*)d_in[1];   // bool -> int32 on the wire
    const float* emb    = (const float*)d_in[2];
    const float* cw     = (const float*)d_in[3];
    float*       out    = (float*)d_out;

    int V = in_sizes[2] / 128;          // vocab rows
    int N = in_sizes[0] / 320;          // trees (8*40 tokens each)

    ek_kernel<<<(V + 7) / 8, 256>>>(emb, cw, V);
    tree_kernel<<<(N + 7) / 8, 256>>>(tokens, masks, emb, out, N, V);
}

// round 3
// speedup vs baseline: 1.2802x; 1.2802x over previous
#include <cuda_runtime.h>
#include <cuda_fp16.h>
#include <cstdint>

#define EKV 30016
__device__ float  d_E[EKV];              // E[v] = embedding[v] . context_weight (fp32)
__device__ __half d_EH[EKV * 128];       // fp16 shadow of the embedding table

static __device__ __forceinline__ float wsum(float v) {
#pragma unroll
    for (int o = 16; o; o >>= 1) v += __shfl_xor_sync(0xffffffffu, v, o);
    return v;
}
static __device__ __forceinline__ float wmax(float v) {
#pragma unroll
    for (int o = 16; o; o >>= 1) v = fmaxf(v, __shfl_xor_sync(0xffffffffu, v, o));
    return v;
}

// Pre-kernel: E[v] = emb[v].cw (fp32) and d_EH[v] = fp16(emb[v]). One warp/row.
__global__ void ek_kernel(const float* __restrict__ emb,
                          const float* __restrict__ cw, int V) {
    int w = (blockIdx.x * blockDim.x + threadIdx.x) >> 5;
    int lane = threadIdx.x & 31;
    if (w >= V || w >= EKV) return;
    float4 e = reinterpret_cast<const float4*>(emb)[w * 32 + lane];
    float4 c = reinterpret_cast<const float4*>(cw)[lane];
    // fp16 shadow: lane owns dims [4l,4l+4) -> 8 bytes
    __half2 h0 = __floats2half2_rn(e.x, e.y);
    __half2 h1 = __floats2half2_rn(e.z, e.w);
    uint2 pk;
    pk.x = *reinterpret_cast<uint32_t*>(&h0);
    pk.y = *reinterpret_cast<uint32_t*>(&h1);
    reinterpret_cast<uint2*>(d_EH)[w * 32 + lane] = pk;
    float s = wsum(e.x * c.x + e.y * c.y + e.z * c.z + e.w * c.w);
    if (lane == 0) d_E[w] = s;
}

// Main kernel: one warp per tree, lane owns 4 dims. Vector gathers hit the
// fp16 shadow table (8 B/lane); all scalar recursion math stays fp32.
__global__ __launch_bounds__(256) void tree_kernel(
    const int* __restrict__ tokens, const int* __restrict__ masks,
    float* __restrict__ out, int N, int V) {
    const int lane = threadIdx.x & 31;
    const int n = blockIdx.x * (blockDim.x >> 5) + (threadIdx.x >> 5);
    if (n >= N) return;
    const int vmax = min(V, EKV) - 1;
    const int* tk = tokens + n * 320;
    const int* mk = masks + n * 320;
    const uint2* eh = reinterpret_cast<const uint2*>(d_EH);

    // ---------- leaf level d = 7 ----------
    int t0 = tk[7 * 40 + lane];
    bool m0 = mk[7 * 40 + lane] != 0;
    bool v0 = m0 && (t0 >= 0);
    t0 = min(max(t0, 0), vmax);
    int t1 = 0; bool m1 = false, v1 = false;
    if (lane < 8) {
        t1 = tk[7 * 40 + 32 + lane];
        m1 = mk[7 * 40 + 32 + lane] != 0;
        v1 = m1 && (t1 >= 0);
        t1 = min(max(t1, 0), vmax);
    }
    int prev_cnt = __popc(__ballot_sync(0xffffffffu, m0)) +
                   __popc(__ballot_sync(0xffffffffu, (lane < 8) && m1));

    float c0 = v0 ? 1.f : 0.f;
    float c1 = v1 ? 1.f : 0.f;

    float4 acc = make_float4(0.f, 0.f, 0.f, 0.f);
#pragma unroll
    for (int s = 0; s < 40; ++s) {
        float cs = __shfl_sync(0xffffffffu, (s < 32) ? c0 : c1, s & 31);
        int   ts = __shfl_sync(0xffffffffu, (s < 32) ? t0 : t1, s & 31);
        uint2 pk = eh[ts * 32 + lane];
        float2 r0 = __half22float2(*reinterpret_cast<__half2*>(&pk.x));
        float2 r1 = __half22float2(*reinterpret_cast<__half2*>(&pk.y));
        acc.x = fmaf(cs, r0.x, acc.x);
        acc.y = fmaf(cs, r0.y, acc.y);
        acc.z = fmaf(cs, r1.x, acc.z);
        acc.w = fmaf(cs, r1.y, acc.w);
    }
    // p = pooled . cw = sum over valid slots of E[token]
    float e0 = d_E[t0];
    float e1 = (lane < 8) ? d_E[t1] : 0.f;
    float p = wsum((v0 ? e0 : 0.f) + (v1 ? e1 : 0.f));

    // ---------- levels d = 6 .. 0 ----------
#pragma unroll 1
    for (int d = 6; d >= 0; --d) {
        t0 = tk[d * 40 + lane];
        m0 = mk[d * 40 + lane] != 0;
        v0 = m0 && (t0 >= 0);
        t0 = min(max(t0, 0), vmax);
        t1 = 0; m1 = false; v1 = false;
        if (lane < 8) {
            t1 = tk[d * 40 + 32 + lane];
            m1 = mk[d * 40 + 32 + lane] != 0;
            v1 = m1 && (t1 >= 0);
            t1 = min(max(t1, 0), vmax);
        }
        int cur_cnt = __popc(__ballot_sync(0xffffffffu, m0)) +
                      __popc(__ballot_sync(0xffffffffu, (lane < 8) && m1));
        int nc = max(prev_cnt, 1);   // child count = masks of level d+1
        prev_cnt = cur_cnt;

        e0 = d_E[t0];
        e1 = (lane < 8) ? d_E[t1] : 0.f;
        float g0 = 1.f / (1.f + __expf(-e0));
        float g1 = 1.f / (1.f + __expf(-e1));
        float cc0 = (v0 && (lane < nc)) ? g0 : 0.f;          // gate * child
        float cc1 = (v1 && (32 + lane < nc)) ? g1 : 0.f;
        float h0 = e0 + cc0 * p;                             // attn logit
        float h1 = e1 + cc1 * p;
        float l0 = v0 ? h0 : -1e38f;
        float l1 = v1 ? h1 : -1e38f;
        float mx = wmax(fmaxf(l0, l1));
        float x0 = v0 ? __expf(h0 - mx) : 0.f;
        float x1 = v1 ? __expf(h1 - mx) : 0.f;
        float Z = wsum(x0 + x1);
        float inv = 1.f / Z;
        float a0 = x0 * inv, a1 = x1 * inv;                  // softmax weights
        float A  = wsum(a0 * cc0 + a1 * cc1);                // Σ a_s cc_s
        float pn = wsum(a0 * h0 + a1 * h1);                  // new pooled . cw

        float4 nacc;
        nacc.x = A * acc.x; nacc.y = A * acc.y;
        nacc.z = A * acc.z; nacc.w = A * acc.w;
#pragma unroll
        for (int s = 0; s < 40; ++s) {
            float cs = __shfl_sync(0xffffffffu, (s < 32) ? a0 : a1, s & 31);
            int   ts = __shfl_sync(0xffffffffu, (s < 32) ? t0 : t1, s & 31);
            uint2 pk = eh[ts * 32 + lane];
            float2 r0 = __half22float2(*reinterpret_cast<__half2*>(&pk.x));
            float2 r1 = __half22float2(*reinterpret_cast<__half2*>(&pk.y));
            nacc.x = fmaf(cs, r0.x, nacc.x);
            nacc.y = fmaf(cs, r0.y, nacc.y);
            nacc.z = fmaf(cs, r1.x, nacc.z);
            nacc.w = fmaf(cs, r1.y, nacc.w);
        }
        acc = nacc;
        p = pn;
    }

    reinterpret_cast<float4*>(out)[n * 32 + lane] = acc;
}

extern "C" void kernel_launch(void* const* d_in, const int* in_sizes, int n_in,
                              void* d_out, int out_size) {
    const int*   tokens = (const int*)d_in[0];
    const int*   masks  = (const int*)d_in[1];   // bool -> int32 on the wire
    const float* emb    = (const float*)d_in[2];
    const float* cw     = (const float*)d_in[3];
    float*       out    = (float*)d_out;

    int V = in_sizes[2] / 128;          // vocab rows
    int N = in_sizes[0] / 320;          // trees (8*40 tokens each)

    ek_kernel<<<(V + 7) / 8, 256>>>(emb, cw, V);
    tree_kernel<<<(N + 7) / 8, 256>>>(tokens, masks, out, N, V);
}